// round 7
// baseline (speedup 1.0000x reference)
#include <cuda_runtime.h>

#define D 128
#define N_USERS 50000
#define N_ITEMS 100000
#define N_GROUPS 20000
#define NNZ_U 1000000
#define NNZ_I 2000000
#define NNZ_F 3000000
#define NORM_ROWS (N_USERS + N_ITEMS)
#define NORM_SIZE (NORM_ROWS * D)
#define MSG_SIZE (N_GROUPS * D)

// Fixed-capacity row buckets (Poisson means 50/100/20; caps are >8 sigma).
#define CAP_U 128
#define CAP_I 192
#define CAP_F 64

typedef unsigned long long ull;

// ---------------------------------------------------------------------------
// Device-global scratch (no cudaMalloc allowed).
// ---------------------------------------------------------------------------
__device__ float g_umsg[MSG_SIZE];
__device__ float g_imsg[MSG_SIZE];
__device__ __align__(16) float g_WT[2 * D * D];   // WT[k][d] = W[d][k]

__device__ int g_cnt_u[N_GROUPS];          // atomic cursors / row lengths
__device__ int g_cnt_i[N_GROUPS];
__device__ int g_cnt_f[NORM_ROWS];

__device__ uint2 g_edge_u[N_GROUPS * CAP_U];   // (col, val_bits) bucketed by row
__device__ uint2 g_edge_i[N_GROUPS * CAP_I];
__device__ uint2 g_edge_f[NORM_ROWS * CAP_F];

// ---------------------------------------------------------------------------
// Packed f32x2 helpers.
// ---------------------------------------------------------------------------
__device__ __forceinline__ ull pack2(float lo, float hi) {
    ull r;
    asm("mov.b64 %0, {%1, %2};" : "=l"(r) : "f"(lo), "f"(hi));
    return r;
}
__device__ __forceinline__ void unpack2(ull v, float& lo, float& hi) {
    asm("mov.b64 {%0, %1}, %2;" : "=f"(lo), "=f"(hi) : "l"(v));
}
__device__ __forceinline__ void fma2(ull& acc, ull a, ull b) {
    asm("fma.rn.f32x2 %0, %1, %2, %0;" : "+l"(acc) : "l"(a), "l"(b));
}

// ---------------------------------------------------------------------------
// Setup: zero cursors + transpose W.
// ---------------------------------------------------------------------------
__global__ void setup_kernel(const float* __restrict__ W) {
    int i = blockIdx.x * blockDim.x + threadIdx.x;
    int stride = gridDim.x * blockDim.x;
    for (int j = i; j < N_GROUPS; j += stride) { g_cnt_u[j] = 0; g_cnt_i[j] = 0; }
    for (int j = i; j < NORM_ROWS; j += stride) g_cnt_f[j] = 0;
    for (int m = i; m < 2 * D * D; m += stride) {
        int k = m >> 7;
        int d = m & (D - 1);
        g_WT[m] = W[d * (2 * D) + k];
    }
}

// ---------------------------------------------------------------------------
// Bucket scatter, 4-way software-pipelined.
// ---------------------------------------------------------------------------
__device__ __forceinline__ void scatter_range(const int* __restrict__ rows,
                                              const int* __restrict__ cols,
                                              const float* __restrict__ vals,
                                              int* __restrict__ cur,
                                              uint2* __restrict__ edges,
                                              int nnz, int bid, int nb, int cap) {
    int tid = bid * blockDim.x + threadIdx.x;
    int stride = nb * blockDim.x;

    int e = tid;
    for (; e + 3 * stride < nnz; e += 4 * stride) {
        int e0 = e, e1 = e + stride, e2 = e + 2 * stride, e3 = e + 3 * stride;
        int r0 = __ldcs(rows + e0), r1 = __ldcs(rows + e1);
        int r2 = __ldcs(rows + e2), r3 = __ldcs(rows + e3);
        int c0 = __ldcs(cols + e0), c1 = __ldcs(cols + e1);
        int c2 = __ldcs(cols + e2), c3 = __ldcs(cols + e3);
        float v0 = __ldcs(vals + e0), v1 = __ldcs(vals + e1);
        float v2 = __ldcs(vals + e2), v3 = __ldcs(vals + e3);
        int p0 = atomicAdd(&cur[r0], 1);
        int p1 = atomicAdd(&cur[r1], 1);
        int p2 = atomicAdd(&cur[r2], 1);
        int p3 = atomicAdd(&cur[r3], 1);
        __stcs(&edges[(size_t)r0 * cap + p0], make_uint2((unsigned)c0, __float_as_uint(v0)));
        __stcs(&edges[(size_t)r1 * cap + p1], make_uint2((unsigned)c1, __float_as_uint(v1)));
        __stcs(&edges[(size_t)r2 * cap + p2], make_uint2((unsigned)c2, __float_as_uint(v2)));
        __stcs(&edges[(size_t)r3 * cap + p3], make_uint2((unsigned)c3, __float_as_uint(v3)));
    }
    for (; e < nnz; e += stride) {
        int r = __ldcs(rows + e);
        int pos = atomicAdd(&cur[r], 1);
        __stcs(&edges[(size_t)r * cap + pos],
               make_uint2((unsigned)__ldcs(cols + e), __float_as_uint(__ldcs(vals + e))));
    }
}

// u+i scatter (independent of f).
__global__ void scatter_ui_kernel(const int* __restrict__ u_rows, const int* __restrict__ u_cols,
                                  const float* __restrict__ u_vals,
                                  const int* __restrict__ i_rows, const int* __restrict__ i_cols,
                                  const float* __restrict__ i_vals) {
    int B_U = gridDim.x / 3;     // 1/3 of blocks to u (1M), 2/3 to i (2M)
    if (blockIdx.x < B_U)
        scatter_range(u_rows, u_cols, u_vals, g_cnt_u, g_edge_u, NNZ_U, blockIdx.x, B_U, CAP_U);
    else
        scatter_range(i_rows, i_cols, i_vals, g_cnt_i, g_edge_i, NNZ_I,
                      blockIdx.x - B_U, gridDim.x - B_U, CAP_I);
}

// f scatter (runs on side stream, overlapped with gather_ui).
__global__ void scatter_f_kernel(const int* __restrict__ f_rows, const int* __restrict__ f_cols,
                                 const float* __restrict__ f_vals) {
    scatter_range(f_rows, f_cols, f_vals, g_cnt_f, g_edge_f, NNZ_F,
                  blockIdx.x, gridDim.x, CAP_F);
}

// ---------------------------------------------------------------------------
// Half-row gather: warp covers 64 columns (float2/lane) of one row,
// processing ALL edges of that row with 16-edge batching.
// Work unit = (row, half). Wavefront traffic identical to full-row version;
// 2x warps + 2x batch depth => ~4x outstanding loads per SM.
// ---------------------------------------------------------------------------
__device__ __forceinline__ void gather_row_half(const int* __restrict__ cnt,
                                                const uint2* __restrict__ edges,
                                                const float* __restrict__ dense,
                                                float* __restrict__ out,
                                                int row, int cap, int lane, int half) {
    int n = cnt[row];
    const uint2* eb = edges + (size_t)row * cap;
    const float2* db = reinterpret_cast<const float2*>(dense) + (half << 5) + lane;

    float accx = 0.f, accy = 0.f;
    int e = 0;
    for (; e + 16 <= n; e += 16) {
        uint2 ed[16];
#pragma unroll
        for (int j = 0; j < 16; j++) ed[j] = __ldcs(eb + e + j);
        float2 x[16];
#pragma unroll
        for (int j = 0; j < 16; j++) x[j] = __ldg(db + (size_t)ed[j].x * 64);
#pragma unroll
        for (int j = 0; j < 16; j++) {
            float v = __uint_as_float(ed[j].y);
            accx += v * x[j].x;
            accy += v * x[j].y;
        }
    }
    for (; e + 4 <= n; e += 4) {
        uint2 ed[4];
#pragma unroll
        for (int j = 0; j < 4; j++) ed[j] = __ldcs(eb + e + j);
        float2 x[4];
#pragma unroll
        for (int j = 0; j < 4; j++) x[j] = __ldg(db + (size_t)ed[j].x * 64);
#pragma unroll
        for (int j = 0; j < 4; j++) {
            float v = __uint_as_float(ed[j].y);
            accx += v * x[j].x;
            accy += v * x[j].y;
        }
    }
    for (; e < n; e++) {
        uint2 ed = __ldcs(eb + e);
        float v  = __uint_as_float(ed.y);
        float2 x = __ldg(db + (size_t)ed.x * 64);
        accx += v * x.x;
        accy += v * x.y;
    }
    __stcs(reinterpret_cast<float2*>(out + (size_t)row * D) + (half << 5) + lane,
           make_float2(accx, accy));
}

// Fused user+item gather, split-half units.
// units: [0, 2*N_GROUPS) user, [2*N_GROUPS, 4*N_GROUPS) item. 8 units/block.
__global__ __launch_bounds__(256) void gather_ui_kernel(const float* __restrict__ user_emb,
                                                        const float* __restrict__ item_emb) {
    int lane = threadIdx.x & 31;
    int unit = blockIdx.x * 8 + (threadIdx.x >> 5);
    if (unit < 2 * N_GROUPS) {
        gather_row_half(g_cnt_u, g_edge_u, user_emb, g_umsg, unit >> 1, CAP_U, lane, unit & 1);
    } else {
        unit -= 2 * N_GROUPS;
        gather_row_half(g_cnt_i, g_edge_i, item_emb, g_imsg, unit >> 1, CAP_I, lane, unit & 1);
    }
}

// Final gather into norm_emb, split-half units.
__global__ __launch_bounds__(256) void gather_f_kernel(const float* __restrict__ msg,
                                                       float* __restrict__ norm) {
    int lane = threadIdx.x & 31;
    int unit = blockIdx.x * 8 + (threadIdx.x >> 5);
    if (unit >= 2 * NORM_ROWS) return;
    gather_row_half(g_cnt_f, g_edge_f, msg, norm, unit >> 1, CAP_F, lane, unit & 1);
}

// ---------------------------------------------------------------------------
// dense_agg: msg[g,d] = sum_k xs[g][k]*WT[k][d] + b[d], packed f32x2.
// ---------------------------------------------------------------------------
#define DG_GROUPS 16
#define XS_PAD 17
__global__ __launch_bounds__(128) void dense_agg_kernel(const float* __restrict__ b,
                                                        float* __restrict__ msg) {
    __shared__ float2 xs2[2 * D * XS_PAD];
    int tid  = threadIdx.x;
    int lane = tid & 31;
    int warp = tid >> 5;
    int gbase = blockIdx.x * DG_GROUPS;

    for (int idx = tid; idx < DG_GROUPS * D; idx += 128) {
        int gi = idx >> 7;
        int c  = idx & (D - 1);
        float vu = g_umsg[(gbase + gi) * D + c];
        float vi = g_imsg[(gbase + gi) * D + c];
        xs2[c * XS_PAD + gi]       = make_float2(vu, vu);
        xs2[(D + c) * XS_PAD + gi] = make_float2(vi, vi);
    }
    __syncthreads();

    float4 b4 = __ldg(reinterpret_cast<const float4*>(b) + lane);
    ull acc01[4], acc23[4];
    ull b01 = pack2(b4.x, b4.y), b23 = pack2(b4.z, b4.w);
#pragma unroll
    for (int j = 0; j < 4; j++) { acc01[j] = b01; acc23[j] = b23; }

    const float4* WT4 = reinterpret_cast<const float4*>(g_WT);
    const ull* xrow = reinterpret_cast<const ull*>(xs2) + warp * 4;

#pragma unroll 4
    for (int k = 0; k < 2 * D; k++) {
        float4 w4 = WT4[k * 32 + lane];
        ull w01 = pack2(w4.x, w4.y);
        ull w23 = pack2(w4.z, w4.w);
        const ull* xk = xrow + k * XS_PAD;
#pragma unroll
        for (int j = 0; j < 4; j++) {
            ull xv = xk[j];
            fma2(acc01[j], w01, xv);
            fma2(acc23[j], w23, xv);
        }
    }

#pragma unroll
    for (int j = 0; j < 4; j++) {
        float4 o;
        unpack2(acc01[j], o.x, o.y);
        unpack2(acc23[j], o.z, o.w);
        int g = gbase + warp * 4 + j;
        reinterpret_cast<float4*>(msg + (size_t)g * D)[lane] = o;
    }
}

// ---------------------------------------------------------------------------
extern "C" void kernel_launch(void* const* d_in, const int* in_sizes, int n_in,
                              void* d_out, int out_size) {
    const float* user_emb = (const float*)d_in[0];
    const float* item_emb = (const float*)d_in[1];
    // d_in[2] = group_emb (unused by reference)
    const int*   u_rows = (const int*)d_in[3];
    const int*   u_cols = (const int*)d_in[4];
    const float* u_vals = (const float*)d_in[5];
    const int*   i_rows = (const int*)d_in[6];
    const int*   i_cols = (const int*)d_in[7];
    const float* i_vals = (const float*)d_in[8];
    const int*   f_rows = (const int*)d_in[9];
    const int*   f_cols = (const int*)d_in[10];
    const float* f_vals = (const float*)d_in[11];
    const float* W_agg  = (const float*)d_in[12];
    const float* b_agg  = (const float*)d_in[13];

    float* out  = (float*)d_out;
    float* norm = out;                  // [150000, 128]
    float* msg  = out + NORM_SIZE;      // [20000, 128]

    static cudaStream_t s2 = nullptr;
    static cudaEvent_t ev_fork = nullptr, ev_join = nullptr;
    if (s2 == nullptr) {
        cudaStreamCreateWithFlags(&s2, cudaStreamNonBlocking);
        cudaEventCreateWithFlags(&ev_fork, cudaEventDisableTiming);
        cudaEventCreateWithFlags(&ev_join, cudaEventDisableTiming);
    }

    const int tpb = 256;

    setup_kernel<<<148, tpb>>>(W_agg);

    // Fork: scatter_f on side stream, overlapped with scatter_ui + gather_ui.
    cudaEventRecord(ev_fork, 0);
    cudaStreamWaitEvent(s2, ev_fork, 0);

    scatter_ui_kernel<<<1184, tpb>>>(u_rows, u_cols, u_vals, i_rows, i_cols, i_vals);
    scatter_f_kernel<<<1184, tpb, 0, s2>>>(f_rows, f_cols, f_vals);

    gather_ui_kernel<<<4 * N_GROUPS / 8, tpb>>>(user_emb, item_emb);

    dense_agg_kernel<<<N_GROUPS / DG_GROUPS, 128>>>(b_agg, msg);

    // Join: gather_f needs both dense (stream 0) and scatter_f (s2).
    cudaEventRecord(ev_join, s2);
    cudaStreamWaitEvent(0, ev_join, 0);

    gather_f_kernel<<<(2 * NORM_ROWS + 7) / 8, tpb>>>(msg, norm);
}

// round 8
// speedup vs baseline: 1.1711x; 1.1711x over previous
#include <cuda_runtime.h>

#define D 128
#define N_USERS 50000
#define N_ITEMS 100000
#define N_GROUPS 20000
#define NNZ_U 1000000
#define NNZ_I 2000000
#define NNZ_F 3000000
#define NORM_ROWS (N_USERS + N_ITEMS)
#define NORM_SIZE (NORM_ROWS * D)
#define MSG_SIZE (N_GROUPS * D)

// Fixed-capacity row buckets (Poisson means 50/100/20; caps are >8 sigma).
#define CAP_U 128
#define CAP_I 192
#define CAP_F 64

typedef unsigned long long ull;

// ---------------------------------------------------------------------------
// Device-global scratch (no cudaMalloc allowed).
// ---------------------------------------------------------------------------
__device__ float g_umsg[MSG_SIZE];
__device__ float g_imsg[MSG_SIZE];
__device__ __align__(16) float g_WT[2 * D * D];   // WT[k][d] = W[d][k]

__device__ int g_cnt_u[N_GROUPS];          // atomic cursors / row lengths
__device__ int g_cnt_i[N_GROUPS];
__device__ int g_cnt_f[NORM_ROWS];

__device__ uint2 g_edge_u[N_GROUPS * CAP_U];   // (col, val_bits) bucketed by row
__device__ uint2 g_edge_i[N_GROUPS * CAP_I];
__device__ uint2 g_edge_f[NORM_ROWS * CAP_F];

// ---------------------------------------------------------------------------
// Packed f32x2 helpers.
// ---------------------------------------------------------------------------
__device__ __forceinline__ ull pack2(float lo, float hi) {
    ull r;
    asm("mov.b64 %0, {%1, %2};" : "=l"(r) : "f"(lo), "f"(hi));
    return r;
}
__device__ __forceinline__ void unpack2(ull v, float& lo, float& hi) {
    asm("mov.b64 {%0, %1}, %2;" : "=f"(lo), "=f"(hi) : "l"(v));
}
__device__ __forceinline__ void fma2(ull& acc, ull a, ull b) {
    asm("fma.rn.f32x2 %0, %1, %2, %0;" : "+l"(acc) : "l"(a), "l"(b));
}

// ---------------------------------------------------------------------------
// Setup: zero cursors + transpose W.
// ---------------------------------------------------------------------------
__global__ void setup_kernel(const float* __restrict__ W) {
    int i = blockIdx.x * blockDim.x + threadIdx.x;
    int stride = gridDim.x * blockDim.x;
    for (int j = i; j < N_GROUPS; j += stride) { g_cnt_u[j] = 0; g_cnt_i[j] = 0; }
    for (int j = i; j < NORM_ROWS; j += stride) g_cnt_f[j] = 0;
    for (int m = i; m < 2 * D * D; m += stride) {
        int k = m >> 7;
        int d = m & (D - 1);
        g_WT[m] = W[d * (2 * D) + k];
    }
}

// ---------------------------------------------------------------------------
// Bucket scatter, 4-way software-pipelined.
// ---------------------------------------------------------------------------
__device__ __forceinline__ void scatter_range(const int* __restrict__ rows,
                                              const int* __restrict__ cols,
                                              const float* __restrict__ vals,
                                              int* __restrict__ cur,
                                              uint2* __restrict__ edges,
                                              int nnz, int bid, int nb, int cap) {
    int tid = bid * blockDim.x + threadIdx.x;
    int stride = nb * blockDim.x;

    int e = tid;
    for (; e + 3 * stride < nnz; e += 4 * stride) {
        int e0 = e, e1 = e + stride, e2 = e + 2 * stride, e3 = e + 3 * stride;
        int r0 = __ldcs(rows + e0), r1 = __ldcs(rows + e1);
        int r2 = __ldcs(rows + e2), r3 = __ldcs(rows + e3);
        int c0 = __ldcs(cols + e0), c1 = __ldcs(cols + e1);
        int c2 = __ldcs(cols + e2), c3 = __ldcs(cols + e3);
        float v0 = __ldcs(vals + e0), v1 = __ldcs(vals + e1);
        float v2 = __ldcs(vals + e2), v3 = __ldcs(vals + e3);
        int p0 = atomicAdd(&cur[r0], 1);
        int p1 = atomicAdd(&cur[r1], 1);
        int p2 = atomicAdd(&cur[r2], 1);
        int p3 = atomicAdd(&cur[r3], 1);
        __stcs(&edges[(size_t)r0 * cap + p0], make_uint2((unsigned)c0, __float_as_uint(v0)));
        __stcs(&edges[(size_t)r1 * cap + p1], make_uint2((unsigned)c1, __float_as_uint(v1)));
        __stcs(&edges[(size_t)r2 * cap + p2], make_uint2((unsigned)c2, __float_as_uint(v2)));
        __stcs(&edges[(size_t)r3 * cap + p3], make_uint2((unsigned)c3, __float_as_uint(v3)));
    }
    for (; e < nnz; e += stride) {
        int r = __ldcs(rows + e);
        int pos = atomicAdd(&cur[r], 1);
        __stcs(&edges[(size_t)r * cap + pos],
               make_uint2((unsigned)__ldcs(cols + e), __float_as_uint(__ldcs(vals + e))));
    }
}

// Fused scatter for all 3 matrices: blocks split 1:2:3 by nnz.
__global__ void scatter_all_kernel(const int* __restrict__ u_rows, const int* __restrict__ u_cols,
                                   const float* __restrict__ u_vals,
                                   const int* __restrict__ i_rows, const int* __restrict__ i_cols,
                                   const float* __restrict__ i_vals,
                                   const int* __restrict__ f_rows, const int* __restrict__ f_cols,
                                   const float* __restrict__ f_vals) {
    int B_U = gridDim.x / 6;          // 1M edges
    int B_I = gridDim.x / 3;          // 2M edges
    if (blockIdx.x < B_U) {
        scatter_range(u_rows, u_cols, u_vals, g_cnt_u, g_edge_u, NNZ_U,
                      blockIdx.x, B_U, CAP_U);
    } else if (blockIdx.x < B_U + B_I) {
        scatter_range(i_rows, i_cols, i_vals, g_cnt_i, g_edge_i, NNZ_I,
                      blockIdx.x - B_U, B_I, CAP_I);
    } else {
        scatter_range(f_rows, f_cols, f_vals, g_cnt_f, g_edge_f, NNZ_F,
                      blockIdx.x - B_U - B_I, gridDim.x - B_U - B_I, CAP_F);
    }
}

// ---------------------------------------------------------------------------
// Full-row gather: one warp per row; 32 lanes x float4 = 128 cols;
// 8-edge batching. (Best measured form: R4/R6.)
// ---------------------------------------------------------------------------
__device__ __forceinline__ void gather_row(const int* __restrict__ cnt,
                                           const uint2* __restrict__ edges,
                                           const float* __restrict__ dense,
                                           float* __restrict__ out,
                                           int row, int cap, int lane) {
    int n = cnt[row];
    const uint2* eb = edges + (size_t)row * cap;
    const float4* db = reinterpret_cast<const float4*>(dense) + lane;

    float4 acc = make_float4(0.f, 0.f, 0.f, 0.f);
    int e = 0;
    for (; e + 8 <= n; e += 8) {
        uint2 ed[8];
#pragma unroll
        for (int j = 0; j < 8; j++) ed[j] = __ldcs(eb + e + j);
        float4 x[8];
#pragma unroll
        for (int j = 0; j < 8; j++) x[j] = __ldg(db + (size_t)ed[j].x * 32);
#pragma unroll
        for (int j = 0; j < 8; j++) {
            float v = __uint_as_float(ed[j].y);
            acc.x += v * x[j].x;
            acc.y += v * x[j].y;
            acc.z += v * x[j].z;
            acc.w += v * x[j].w;
        }
    }
    for (; e < n; e++) {
        uint2 ed = __ldcs(eb + e);
        float v  = __uint_as_float(ed.y);
        float4 x = __ldg(db + (size_t)ed.x * 32);
        acc.x += v * x.x; acc.y += v * x.y; acc.z += v * x.z; acc.w += v * x.w;
    }
    __stcs(reinterpret_cast<float4*>(out + (size_t)row * D) + lane, acc);
}

// Fused user+item gather: blocks [0, 2500) = user rows, [2500, 5000) = item rows.
__global__ __launch_bounds__(256) void gather_ui_kernel(const float* __restrict__ user_emb,
                                                        const float* __restrict__ item_emb) {
    const int B_U = N_GROUPS / 8;   // 2500 blocks, 8 warps each
    int lane = threadIdx.x & 31;
    int warp = threadIdx.x >> 5;
    if (blockIdx.x < B_U) {
        int row = blockIdx.x * 8 + warp;
        gather_row(g_cnt_u, g_edge_u, user_emb, g_umsg, row, CAP_U, lane);
    } else {
        int row = (blockIdx.x - B_U) * 8 + warp;
        gather_row(g_cnt_i, g_edge_i, item_emb, g_imsg, row, CAP_I, lane);
    }
}

// Final gather into norm_emb.
__global__ __launch_bounds__(256) void gather_f_kernel(const float* __restrict__ msg,
                                                       float* __restrict__ norm) {
    int row = blockIdx.x * 8 + (threadIdx.x >> 5);
    int lane = threadIdx.x & 31;
    if (row >= NORM_ROWS) return;
    gather_row(g_cnt_f, g_edge_f, msg, norm, row, CAP_F, lane);
}

// ---------------------------------------------------------------------------
// dense_agg: msg[g,d] = sum_k xs[g][k]*WT[k][d] + b[d], packed f32x2.
// Block = 128 threads (4 warps), 16 groups/block (warp w -> groups 4w..4w+3).
// ---------------------------------------------------------------------------
#define DG_GROUPS 16
#define XS_PAD 17
__global__ __launch_bounds__(128) void dense_agg_kernel(const float* __restrict__ b,
                                                        float* __restrict__ msg) {
    __shared__ float2 xs2[2 * D * XS_PAD];
    int tid  = threadIdx.x;
    int lane = tid & 31;
    int warp = tid >> 5;
    int gbase = blockIdx.x * DG_GROUPS;

    for (int idx = tid; idx < DG_GROUPS * D; idx += 128) {
        int gi = idx >> 7;
        int c  = idx & (D - 1);
        float vu = g_umsg[(gbase + gi) * D + c];
        float vi = g_imsg[(gbase + gi) * D + c];
        xs2[c * XS_PAD + gi]       = make_float2(vu, vu);
        xs2[(D + c) * XS_PAD + gi] = make_float2(vi, vi);
    }
    __syncthreads();

    float4 b4 = __ldg(reinterpret_cast<const float4*>(b) + lane);
    ull acc01[4], acc23[4];
    ull b01 = pack2(b4.x, b4.y), b23 = pack2(b4.z, b4.w);
#pragma unroll
    for (int j = 0; j < 4; j++) { acc01[j] = b01; acc23[j] = b23; }

    const float4* WT4 = reinterpret_cast<const float4*>(g_WT);
    const ull* xrow = reinterpret_cast<const ull*>(xs2) + warp * 4;

#pragma unroll 4
    for (int k = 0; k < 2 * D; k++) {
        float4 w4 = WT4[k * 32 + lane];
        ull w01 = pack2(w4.x, w4.y);
        ull w23 = pack2(w4.z, w4.w);
        const ull* xk = xrow + k * XS_PAD;
#pragma unroll
        for (int j = 0; j < 4; j++) {
            ull xv = xk[j];
            fma2(acc01[j], w01, xv);
            fma2(acc23[j], w23, xv);
        }
    }

#pragma unroll
    for (int j = 0; j < 4; j++) {
        float4 o;
        unpack2(acc01[j], o.x, o.y);
        unpack2(acc23[j], o.z, o.w);
        int g = gbase + warp * 4 + j;
        reinterpret_cast<float4*>(msg + (size_t)g * D)[lane] = o;
    }
}

// ---------------------------------------------------------------------------
extern "C" void kernel_launch(void* const* d_in, const int* in_sizes, int n_in,
                              void* d_out, int out_size) {
    const float* user_emb = (const float*)d_in[0];
    const float* item_emb = (const float*)d_in[1];
    // d_in[2] = group_emb (unused by reference)
    const int*   u_rows = (const int*)d_in[3];
    const int*   u_cols = (const int*)d_in[4];
    const float* u_vals = (const float*)d_in[5];
    const int*   i_rows = (const int*)d_in[6];
    const int*   i_cols = (const int*)d_in[7];
    const float* i_vals = (const float*)d_in[8];
    const int*   f_rows = (const int*)d_in[9];
    const int*   f_cols = (const int*)d_in[10];
    const float* f_vals = (const float*)d_in[11];
    const float* W_agg  = (const float*)d_in[12];
    const float* b_agg  = (const float*)d_in[13];

    float* out  = (float*)d_out;
    float* norm = out;                  // [150000, 128]
    float* msg  = out + NORM_SIZE;      // [20000, 128]

    const int tpb = 256;

    // Single stream, no overlap (R6 fork/join measured as a net loss).
    // 1 setup, 2 scatter, 3 gather_ui, 4 dense, 5 gather_f
    setup_kernel<<<148, tpb>>>(W_agg);

    scatter_all_kernel<<<1184, tpb>>>(u_rows, u_cols, u_vals,
                                      i_rows, i_cols, i_vals,
                                      f_rows, f_cols, f_vals);

    gather_ui_kernel<<<2 * (N_GROUPS / 8), tpb>>>(user_emb, item_emb);

    dense_agg_kernel<<<N_GROUPS / DG_GROUPS, 128>>>(b_agg, msg);

    gather_f_kernel<<<(NORM_ROWS + 7) / 8, tpb>>>(msg, norm);
}